// round 15
// baseline (speedup 1.0000x reference)
#include <cuda_runtime.h>
#include <cuda_fp16.h>
#include <math.h>
#include <stdint.h>

#define NN 50000
#define EE 1600000
#define D 128
#define DAGG 384
#define DCAT 1152
#define CAP 128
#define ROWB 192
#define AVG_D_LOG_F 3.4965075614664802f

// ---------------- static scratch --------------------------------------------
__device__ int g_cnt[NN];
__device__ int g_srcl[(size_t)NN * CAP];
__device__ float g_e1[NN];
__device__ __align__(16) uint8_t g_h8[(size_t)NN * ROWB];    // int8 payload + fp16 scales
__device__ __align__(16) __half g_aggh[(size_t)NN * DAGG];   // agg fp16 [N,384]
__device__ __align__(16) __half g_Wh[(size_t)DCAT * D];      // W fp16 [1152,128]

// ---------------- helpers ---------------------------------------------------
__device__ __forceinline__ uint2 pack4h(float4 v) {
    uint2 r;
    __half2 lo = __floats2half2_rn(v.x, v.y);
    __half2 hi = __floats2half2_rn(v.z, v.w);
    r.x = *reinterpret_cast<uint32_t*>(&lo);
    r.y = *reinterpret_cast<uint32_t*>(&hi);
    return r;
}

__device__ __forceinline__ void mma_f16(float* c, const uint32_t* a,
                                        uint32_t b0, uint32_t b1) {
    asm volatile(
        "mma.sync.aligned.m16n8k16.row.col.f32.f16.f16.f32 "
        "{%0,%1,%2,%3}, {%4,%5,%6,%7}, {%8,%9}, {%0,%1,%2,%3};\n"
        : "+f"(c[0]), "+f"(c[1]), "+f"(c[2]), "+f"(c[3])
        : "r"(a[0]), "r"(a[1]), "r"(a[2]), "r"(a[3]), "r"(b0), "r"(b1));
}

__device__ __forceinline__ void ldm_x4(uint32_t* r, uint32_t addr) {
    asm volatile("ldmatrix.sync.aligned.m8n8.x4.shared.b16 {%0,%1,%2,%3}, [%4];"
                 : "=r"(r[0]), "=r"(r[1]), "=r"(r[2]), "=r"(r[3]) : "r"(addr));
}

__device__ __forceinline__ void ldm_x4t(uint32_t* r, uint32_t addr) {
    asm volatile("ldmatrix.sync.aligned.m8n8.x4.trans.shared.b16 {%0,%1,%2,%3}, [%4];"
                 : "=r"(r[0]), "=r"(r[1]), "=r"(r[2]), "=r"(r[3]) : "r"(addr));
}

__device__ __forceinline__ void cp16(uint32_t smem_addr, const void* gptr) {
    asm volatile("cp.async.cg.shared.global [%0], [%1], 16;\n"
                 :: "r"(smem_addr), "l"(gptr));
}

__device__ __forceinline__ uint32_t hscale(uint32_t a, uint32_t coef2) {
    __half2 r = __hmul2(*reinterpret_cast<__half2*>(&a),
                        *reinterpret_cast<__half2*>(&coef2));
    return *reinterpret_cast<uint32_t*>(&r);
}

__device__ __forceinline__ float4 dq4(uint32_t u, float sc) {
    float4 v;
    v.x = (float)(int8_t)(u)         * sc;
    v.y = (float)(int8_t)(u >> 8)    * sc;
    v.z = (float)(int8_t)(u >> 16)   * sc;
    v.w = (float)(int8_t)(u >> 24)   * sc;
    return v;
}

// ---------------- kernel 1: fused prep + bucket fill + per-group quant -------
#define FILLB 782     // 200000 threads x 8 edges
#define QUANTB 6250   // warp-per-node, 8 warps/block
#define WCONVB 576
#define E1B 196
#define PREPGRID (FILLB + QUANTB + WCONVB + E1B)

__global__ void k_prepfill(const int4* __restrict__ src4, const int4* __restrict__ dst4,
                           const float* __restrict__ h, const float* __restrict__ eig,
                           const float* __restrict__ W) {
    int b = blockIdx.x;
    int t = threadIdx.x;
    if (b < FILLB) {
        int i = b * 256 + t;
        if (i >= 200000) return;
        int4 d0 = dst4[i];
        int4 s0 = src4[i];
        int4 d1 = dst4[i + 200000];
        int4 s1 = src4[i + 200000];
        int p0 = atomicAdd(&g_cnt[d0.x], 1);
        int p1 = atomicAdd(&g_cnt[d0.y], 1);
        int p2 = atomicAdd(&g_cnt[d0.z], 1);
        int p3 = atomicAdd(&g_cnt[d0.w], 1);
        int p4 = atomicAdd(&g_cnt[d1.x], 1);
        int p5 = atomicAdd(&g_cnt[d1.y], 1);
        int p6 = atomicAdd(&g_cnt[d1.z], 1);
        int p7 = atomicAdd(&g_cnt[d1.w], 1);
        g_srcl[(size_t)d0.x * CAP + p0] = s0.x;
        g_srcl[(size_t)d0.y * CAP + p1] = s0.y;
        g_srcl[(size_t)d0.z * CAP + p2] = s0.z;
        g_srcl[(size_t)d0.w * CAP + p3] = s0.w;
        g_srcl[(size_t)d1.x * CAP + p4] = s1.x;
        g_srcl[(size_t)d1.y * CAP + p5] = s1.y;
        g_srcl[(size_t)d1.z * CAP + p6] = s1.z;
        g_srcl[(size_t)d1.w * CAP + p7] = s1.w;
    } else if (b < FILLB + QUANTB) {
        int node = (b - FILLB) * 8 + (t >> 5);
        int lane = t & 31;
        if (node >= NN) return;
        float4 v = ((const float4*)h)[(size_t)node * 32 + lane];
        // per-lane-group (4 dims) scale, rounded to fp16 BEFORE quantizing
        float am = fmaxf(fmaxf(fabsf(v.x), fabsf(v.y)), fmaxf(fabsf(v.z), fabsf(v.w)));
        __half sc_h = __float2half_rn(am * (1.0f / 127.0f));
        float sc_f = __half2float(sc_h);
        float inv = (sc_f > 0.f) ? 1.0f / sc_f : 0.f;
        int q0 = min(127, max(-127, (int)rintf(v.x * inv)));
        int q1 = min(127, max(-127, (int)rintf(v.y * inv)));
        int q2 = min(127, max(-127, (int)rintf(v.z * inv)));
        int q3 = min(127, max(-127, (int)rintf(v.w * inv)));
        uint32_t packed = ((uint32_t)q0 & 255u) | (((uint32_t)q1 & 255u) << 8) |
                          (((uint32_t)q2 & 255u) << 16) | (((uint32_t)q3 & 255u) << 24);
        uint8_t* row = g_h8 + (size_t)node * ROWB;
        *reinterpret_cast<uint32_t*>(row + lane * 4) = packed;
        *reinterpret_cast<__half*>(row + 128 + lane * 2) = sc_h;
    } else if (b < FILLB + QUANTB + WCONVB) {
        int idx = (b - FILLB - QUANTB) * 256 + t;
        if (idx < DCAT * D)
            g_Wh[idx] = __float2half(W[idx]);
    } else {
        int idx = (b - FILLB - QUANTB - WCONVB) * 256 + t;
        if (idx < NN) g_e1[idx] = eig[(size_t)idx * 4];
    }
}

// ---------------- kernel 2: warp-per-node reduce (int8 + fp16 scales) --------
__global__ __launch_bounds__(256) void k_reduce() {
    int wid = threadIdx.x >> 5;
    int lane = threadIdx.x & 31;
    int node = blockIdx.x * 8 + wid;
    if (node >= NN) return;
    int deg = g_cnt[node];
    size_t base = (size_t)node * CAP;
    float e1d = g_e1[node];
    const uint8_t* hb = g_h8;

    float sx = 0.f, sy = 0.f, sz = 0.f, sw = 0.f;
    float mxx = -3.402823466e38f, mxy = mxx, mxz = mxx, mxw = mxx;
    float dx = 0.f, dy = 0.f, dz = 0.f, dw = 0.f;
    float wsum = 0.f;

    int j = 0;
    for (; j + 8 <= deg; j += 8) {
        int s[8];
        uint32_t u[8];
        float sc[8];
        float e1s[8];
#pragma unroll
        for (int q = 0; q < 8; q++) s[q] = g_srcl[base + j + q];
#pragma unroll
        for (int q = 0; q < 8; q++) {
            const uint8_t* row = hb + (size_t)s[q] * ROWB;
            u[q] = *reinterpret_cast<const uint32_t*>(row + lane * 4);
            sc[q] = __half2float(*reinterpret_cast<const __half*>(row + 128 + lane * 2));
        }
#pragma unroll
        for (int q = 0; q < 8; q++) e1s[q] = g_e1[s[q]];
#pragma unroll
        for (int q = 0; q < 8; q++) {
            float w = fabsf(e1s[q] - e1d);
            float4 v = dq4(u[q], sc[q]);
            sx += v.x; sy += v.y; sz += v.z; sw += v.w;
            mxx = fmaxf(mxx, v.x); mxy = fmaxf(mxy, v.y);
            mxz = fmaxf(mxz, v.z); mxw = fmaxf(mxw, v.w);
            dx = fmaf(w, v.x, dx); dy = fmaf(w, v.y, dy);
            dz = fmaf(w, v.z, dz); dw = fmaf(w, v.w, dw);
            wsum += w;
        }
    }
    for (; j < deg; j++) {
        int s0 = g_srcl[base + j];
        const uint8_t* row = hb + (size_t)s0 * ROWB;
        uint32_t u0 = *reinterpret_cast<const uint32_t*>(row + lane * 4);
        float sc0 = __half2float(*reinterpret_cast<const __half*>(row + 128 + lane * 2));
        float w0 = fabsf(g_e1[s0] - e1d);
        float4 v0 = dq4(u0, sc0);
        sx += v0.x; sy += v0.y; sz += v0.z; sw += v0.w;
        mxx = fmaxf(mxx, v0.x); mxy = fmaxf(mxy, v0.y);
        mxz = fmaxf(mxz, v0.z); mxw = fmaxf(mxw, v0.w);
        dx = fmaf(w0, v0.x, dx); dy = fmaf(w0, v0.y, dy);
        dz = fmaf(w0, v0.z, dz); dw = fmaf(w0, v0.w, dw);
        wsum += w0;
    }

    float invd = 1.f / (float)(deg > 0 ? deg : 1);
    float invw = 1.f / (wsum + 1e-30f);
    if (deg == 0) { mxx = 0.f; mxy = 0.f; mxz = 0.f; mxw = 0.f; }

    uint2* o = reinterpret_cast<uint2*>(g_aggh) + (size_t)node * 96;
    o[lane]      = pack4h(make_float4(sx * invd, sy * invd, sz * invd, sw * invd));
    o[32 + lane] = pack4h(make_float4(mxx, mxy, mxz, mxw));
    o[64 + lane] = pack4h(make_float4(dx * invw, dy * invw, dz * invw, dw * invw));
}

// ---------------- kernel 3: fused triple-B GEMM, BK=64, 2-stage --------------
#define BM 128
#define BN 64
#define BK 64
#define NKT (DAGG / BK)  // 6
#define A_STAGE 18432
#define B_OFF (2 * A_STAGE)
#define B_STAGE 27648
#define COEF_OFF (B_OFF + 2 * B_STAGE)
#define SMEM_BYTES (COEF_OFF + 3 * 128 * 4) // 93696

__global__ __launch_bounds__(256, 2) void k_gemm(
    const float* __restrict__ h, const float* __restrict__ snorm,
    const float* __restrict__ bias, const float* __restrict__ gamma,
    const float* __restrict__ beta, const float* __restrict__ mean,
    const float* __restrict__ var, float* __restrict__ out) {
    extern __shared__ char smc[];
    uint32_t sb = (uint32_t)__cvta_generic_to_shared(smc);
    float* samp = (float*)(smc + COEF_OFF);
    float* satt = samp + BM;
    float* ssn = satt + BM;

    int tid = threadIdx.x;
    int wid = tid >> 5;
    int lane = tid & 31;
    int t = lane & 3;
    int gid = lane >> 2;
    int wr = wid & 3;
    int wc = wid >> 2;
    int rowBlock = (blockIdx.x >> 1) * BM;
    int colBlock = (blockIdx.x & 1) * BN;

    for (int i = tid; i < BM; i += 256) {
        int r = rowBlock + i;
        float amp = 0.f, att = 0.f, sn = 0.f;
        if (r < NN) {
            int deg = g_cnt[r];
            float logD = logf((float)deg + 1.0f);
            amp = logD * (1.0f / AVG_D_LOG_F);
            att = fminf(AVG_D_LOG_F / fmaxf(logD, 1e-6f), 60000.f);
            sn = snorm[r];
        }
        samp[i] = amp;
        satt[i] = att;
        ssn[i] = sn;
    }

    const __half* a_src[4];
    uint32_t a_dst[4];
#pragma unroll
    for (int i = 0; i < 4; i++) {
        int c = tid + 256 * i;
        int row = c >> 3, kc = c & 7;
        int gr = rowBlock + row; if (gr > NN - 1) gr = NN - 1;
        a_src[i] = g_aggh + (size_t)gr * DAGG + kc * 8;
        a_dst[i] = sb + row * 144 + kc * 16;
    }

    const __half* b_src[6];
    uint32_t b_dst[6];
#pragma unroll
    for (int i = 0; i < 6; i++) {
        int c = tid + 256 * i;
        int g = c >> 9;
        int rem = c & 511;
        int krow = rem >> 3;
        int nc = rem & 7;
        b_src[i] = g_Wh + ((size_t)g * DAGG + krow) * D + colBlock + nc * 8;
        b_dst[i] = sb + B_OFF + g * 9216 + krow * 144 + nc * 16;
    }

    float c[2][4][4];
#pragma unroll
    for (int mt = 0; mt < 2; mt++)
#pragma unroll
        for (int nt = 0; nt < 4; nt++)
#pragma unroll
            for (int k = 0; k < 4; k++) c[mt][nt][k] = 0.f;

#pragma unroll
    for (int i = 0; i < 4; i++) cp16(a_dst[i], a_src[i]);
#pragma unroll
    for (int i = 0; i < 6; i++) cp16(b_dst[i], b_src[i]);
    asm volatile("cp.async.commit_group;\n");

    __syncthreads();

    uint32_t amp2[2][2], att2[2][2];
#pragma unroll
    for (int mt = 0; mt < 2; mt++) {
        int r0 = wr * 32 + mt * 16 + gid;
        __half2 a0 = __float2half2_rn(samp[r0]);
        __half2 a1 = __float2half2_rn(samp[r0 + 8]);
        __half2 t0 = __float2half2_rn(satt[r0]);
        __half2 t1 = __float2half2_rn(satt[r0 + 8]);
        amp2[mt][0] = *reinterpret_cast<uint32_t*>(&a0);
        amp2[mt][1] = *reinterpret_cast<uint32_t*>(&a1);
        att2[mt][0] = *reinterpret_cast<uint32_t*>(&t0);
        att2[mt][1] = *reinterpret_cast<uint32_t*>(&t1);
    }

    uint32_t a_lm = sb + (wr * 32 + (lane & 15)) * 144 + ((lane >> 4) << 4);
    uint32_t b_lm = sb + B_OFF + (lane & 15) * 144 + wc * 64 + ((lane >> 4) << 4);

    for (int kt = 0; kt < NKT; kt++) {
        int buf = kt & 1;
        if (kt + 1 < NKT) {
            size_t koff = (size_t)(kt + 1) * BK;
            uint32_t ao = (buf ^ 1) * A_STAGE;
#pragma unroll
            for (int i = 0; i < 4; i++) cp16(a_dst[i] + ao, a_src[i] + koff);
            uint32_t bo = (buf ^ 1) * B_STAGE;
#pragma unroll
            for (int i = 0; i < 6; i++) cp16(b_dst[i] + bo, b_src[i] + koff * D);
            asm volatile("cp.async.commit_group;\n");
            asm volatile("cp.async.wait_group 1;\n");
        } else {
            asm volatile("cp.async.wait_group 0;\n");
        }
        __syncthreads();

        uint32_t a_base = a_lm + buf * A_STAGE;
        uint32_t b_base = b_lm + buf * B_STAGE;
#pragma unroll
        for (int ks = 0; ks < 4; ks++) {
            uint32_t a[2][4];
            ldm_x4(a[0], a_base + ks * 32);
            ldm_x4(a[1], a_base + 16 * 144 + ks * 32);
#pragma unroll
            for (int g = 0; g < 3; g++) {
                uint32_t bfr[2][4];
#pragma unroll
                for (int p = 0; p < 2; p++)
                    ldm_x4t(bfr[p], b_base + g * 9216 + ks * 2304 + p * 32);
                uint32_t au[2][4];
#pragma unroll
                for (int mt = 0; mt < 2; mt++) {
                    if (g == 0) {
                        au[mt][0] = a[mt][0]; au[mt][1] = a[mt][1];
                        au[mt][2] = a[mt][2]; au[mt][3] = a[mt][3];
                    } else if (g == 1) {
                        au[mt][0] = hscale(a[mt][0], amp2[mt][0]);
                        au[mt][1] = hscale(a[mt][1], amp2[mt][1]);
                        au[mt][2] = hscale(a[mt][2], amp2[mt][0]);
                        au[mt][3] = hscale(a[mt][3], amp2[mt][1]);
                    } else {
                        au[mt][0] = hscale(a[mt][0], att2[mt][0]);
                        au[mt][1] = hscale(a[mt][1], att2[mt][1]);
                        au[mt][2] = hscale(a[mt][2], att2[mt][0]);
                        au[mt][3] = hscale(a[mt][3], att2[mt][1]);
                    }
                }
#pragma unroll
                for (int p = 0; p < 2; p++) {
#pragma unroll
                    for (int mt = 0; mt < 2; mt++) {
                        mma_f16(c[mt][p * 2], au[mt], bfr[p][0], bfr[p][1]);
                        mma_f16(c[mt][p * 2 + 1], au[mt], bfr[p][2], bfr[p][3]);
                    }
                }
            }
        }
        __syncthreads();
    }

    // fused epilogue
#pragma unroll
    for (int nt = 0; nt < 4; nt++) {
        int col = colBlock + wc * 32 + nt * 8 + 2 * t;
        float2 bi = *(const float2*)(bias + col);
        float2 mn = *(const float2*)(mean + col);
        float2 vr = *(const float2*)(var + col);
        float2 gm = *(const float2*)(gamma + col);
        float2 bt = *(const float2*)(beta + col);
        float sc0 = rsqrtf(vr.x + 1e-5f) * gm.x;
        float sc1 = rsqrtf(vr.y + 1e-5f) * gm.y;
        float sh0 = bt.x - mn.x * sc0;
        float sh1 = bt.y - mn.y * sc1;
#pragma unroll
        for (int mt = 0; mt < 2; mt++) {
#pragma unroll
            for (int p = 0; p < 2; p++) {
                int rloc = wr * 32 + mt * 16 + gid + p * 8;
                int r = rowBlock + rloc;
                if (r < NN) {
                    float sn = ssn[rloc];
                    float v0 = (c[mt][nt][p * 2 + 0] + bi.x) * sn;
                    float v1 = (c[mt][nt][p * 2 + 1] + bi.y) * sn;
                    v0 = fmaxf(fmaf(v0, sc0, sh0), 0.f);
                    v1 = fmaxf(fmaf(v1, sc1, sh1), 0.f);
                    float2 hres = *(const float2*)(h + (size_t)r * D + col);
                    *(float2*)(out + (size_t)r * D + col) =
                        make_float2(hres.x + v0, hres.y + v1);
                }
            }
        }
    }
}

// ---------------- launch ----------------------------------------------------
extern "C" void kernel_launch(void* const* d_in, const int* in_sizes, int n_in,
                              void* d_out, int out_size) {
    const float* h = (const float*)d_in[0];
    const float* eig = (const float*)d_in[1];
    const float* snorm = (const float*)d_in[2];
    const float* W = (const float*)d_in[3];
    const float* bias = (const float*)d_in[4];
    const float* gamma = (const float*)d_in[5];
    const float* beta = (const float*)d_in[6];
    const float* mean = (const float*)d_in[7];
    const float* var = (const float*)d_in[8];
    const int* esrc = (const int*)d_in[9];
    const int* edst = (const int*)d_in[10];
    float* out = (float*)d_out;

    // Host-side, non-stream, idempotent: capture-safe (no guard).
    cudaFuncSetAttribute(k_gemm, cudaFuncAttributeMaxDynamicSharedMemorySize,
                         SMEM_BYTES);

    void* cntPtr = nullptr;
    cudaGetSymbolAddress(&cntPtr, g_cnt);
    cudaMemsetAsync(cntPtr, 0, NN * sizeof(int));

    k_prepfill<<<PREPGRID, 256>>>((const int4*)esrc, (const int4*)edst, h, eig, W);
    k_reduce<<<(NN + 7) / 8, 256>>>();
    k_gemm<<<((NN + BM - 1) / BM) * 2, 256, SMEM_BYTES>>>(h, snorm, bias, gamma,
                                                          beta, mean, var, out);
}

// round 16
// speedup vs baseline: 1.1120x; 1.1120x over previous
#include <cuda_runtime.h>
#include <cuda_fp16.h>
#include <math.h>
#include <stdint.h>

#define NN 50000
#define EE 1600000
#define D 128
#define DAGG 384
#define DCAT 1152
#define CAP 128
#define AVG_D_LOG_F 3.4965075614664802f

// ---------------- static scratch --------------------------------------------
__device__ int g_cnt[NN];
__device__ int g_srcl[(size_t)NN * CAP];
__device__ float g_e1[NN];
__device__ __align__(16) __half g_hh[(size_t)NN * D];       // h in fp16
__device__ __align__(16) __half g_aggh[(size_t)NN * DAGG];  // agg fp16 [N,384]
__device__ __align__(16) __half g_Wh[(size_t)DCAT * D];     // W fp16 [1152,128]

// ---------------- helpers ---------------------------------------------------
__device__ __forceinline__ float4 h4conv(uint2 u) {
    __half2 a = *reinterpret_cast<__half2*>(&u.x);
    __half2 b = *reinterpret_cast<__half2*>(&u.y);
    float2 fa = __half22float2(a);
    float2 fb = __half22float2(b);
    return make_float4(fa.x, fa.y, fb.x, fb.y);
}

__device__ __forceinline__ uint2 pack4(float4 v) {
    uint2 r;
    __half2 lo = __floats2half2_rn(v.x, v.y);
    __half2 hi = __floats2half2_rn(v.z, v.w);
    r.x = *reinterpret_cast<uint32_t*>(&lo);
    r.y = *reinterpret_cast<uint32_t*>(&hi);
    return r;
}

__device__ __forceinline__ void mma_f16(float* c, const uint32_t* a,
                                        uint32_t b0, uint32_t b1) {
    asm volatile(
        "mma.sync.aligned.m16n8k16.row.col.f32.f16.f16.f32 "
        "{%0,%1,%2,%3}, {%4,%5,%6,%7}, {%8,%9}, {%0,%1,%2,%3};\n"
        : "+f"(c[0]), "+f"(c[1]), "+f"(c[2]), "+f"(c[3])
        : "r"(a[0]), "r"(a[1]), "r"(a[2]), "r"(a[3]), "r"(b0), "r"(b1));
}

__device__ __forceinline__ void ldm_x4(uint32_t* r, uint32_t addr) {
    asm volatile("ldmatrix.sync.aligned.m8n8.x4.shared.b16 {%0,%1,%2,%3}, [%4];"
                 : "=r"(r[0]), "=r"(r[1]), "=r"(r[2]), "=r"(r[3]) : "r"(addr));
}

__device__ __forceinline__ void ldm_x4t(uint32_t* r, uint32_t addr) {
    asm volatile("ldmatrix.sync.aligned.m8n8.x4.trans.shared.b16 {%0,%1,%2,%3}, [%4];"
                 : "=r"(r[0]), "=r"(r[1]), "=r"(r[2]), "=r"(r[3]) : "r"(addr));
}

__device__ __forceinline__ void cp16(uint32_t smem_addr, const void* gptr) {
    asm volatile("cp.async.cg.shared.global [%0], [%1], 16;\n"
                 :: "r"(smem_addr), "l"(gptr));
}

__device__ __forceinline__ uint32_t hscale(uint32_t a, uint32_t coef2) {
    __half2 r = __hmul2(*reinterpret_cast<__half2*>(&a),
                        *reinterpret_cast<__half2*>(&coef2));
    return *reinterpret_cast<uint32_t*>(&r);
}

// ---------------- kernel 1: fused prep + bucket fill (high ILP) --------------
#define FILLB 782
#define HCONVB 1563
#define WCONVB 576
#define E1B 196
#define PREPGRID (FILLB + HCONVB + WCONVB + E1B)

__global__ void k_prepfill(const int4* __restrict__ src4, const int4* __restrict__ dst4,
                           const float* __restrict__ h, const float* __restrict__ eig,
                           const float* __restrict__ W) {
    int b = blockIdx.x;
    int t = threadIdx.x;
    if (b < FILLB) {
        int i = b * 256 + t;
        if (i >= 200000) return;
        int4 d0 = dst4[i];
        int4 s0 = src4[i];
        int4 d1 = dst4[i + 200000];
        int4 s1 = src4[i + 200000];
        int p0 = atomicAdd(&g_cnt[d0.x], 1);
        int p1 = atomicAdd(&g_cnt[d0.y], 1);
        int p2 = atomicAdd(&g_cnt[d0.z], 1);
        int p3 = atomicAdd(&g_cnt[d0.w], 1);
        int p4 = atomicAdd(&g_cnt[d1.x], 1);
        int p5 = atomicAdd(&g_cnt[d1.y], 1);
        int p6 = atomicAdd(&g_cnt[d1.z], 1);
        int p7 = atomicAdd(&g_cnt[d1.w], 1);
        g_srcl[(size_t)d0.x * CAP + p0] = s0.x;
        g_srcl[(size_t)d0.y * CAP + p1] = s0.y;
        g_srcl[(size_t)d0.z * CAP + p2] = s0.z;
        g_srcl[(size_t)d0.w * CAP + p3] = s0.w;
        g_srcl[(size_t)d1.x * CAP + p4] = s1.x;
        g_srcl[(size_t)d1.y * CAP + p5] = s1.y;
        g_srcl[(size_t)d1.z * CAP + p6] = s1.z;
        g_srcl[(size_t)d1.w * CAP + p7] = s1.w;
    } else if (b < FILLB + HCONVB) {
        int i = (b - FILLB) * 256 + t;
        if (i >= 400000) return;
        const float4* h4 = (const float4*)h;
        uint2* o = (uint2*)g_hh;
#pragma unroll
        for (int r = 0; r < 4; r++) {
            int idx = i + r * 400000;
            float4 v = h4[idx];
            o[idx] = pack4(v);
        }
    } else if (b < FILLB + HCONVB + WCONVB) {
        int idx = (b - FILLB - HCONVB) * 256 + t;
        if (idx < DCAT * D)
            g_Wh[idx] = __float2half(W[idx]);
    } else {
        int idx = (b - FILLB - HCONVB - WCONVB) * 256 + t;
        if (idx < NN) g_e1[idx] = eig[(size_t)idx * 4];
    }
}

// ---------------- kernel 2: warp-per-node reduce (8-edge ILP, 4 CTA/SM) ------
__global__ __launch_bounds__(256, 4) void k_reduce() {
    int wid = threadIdx.x >> 5;
    int lane = threadIdx.x & 31;
    int node = blockIdx.x * 8 + wid;
    if (node >= NN) return;
    int deg = g_cnt[node];
    size_t base = (size_t)node * CAP;
    float e1d = g_e1[node];
    const uint2* h2 = reinterpret_cast<const uint2*>(g_hh);

    float sx = 0.f, sy = 0.f, sz = 0.f, sw = 0.f;
    float mxx = -3.402823466e38f, mxy = mxx, mxz = mxx, mxw = mxx;
    float dx = 0.f, dy = 0.f, dz = 0.f, dw = 0.f;
    float wsum = 0.f;

    int j = 0;
    for (; j + 8 <= deg; j += 8) {
        int s[8];
        float w[8];
        uint2 u[8];
#pragma unroll
        for (int q = 0; q < 8; q++) s[q] = g_srcl[base + j + q];
#pragma unroll
        for (int q = 0; q < 8; q++) u[q] = h2[(size_t)s[q] * 32 + lane];
#pragma unroll
        for (int q = 0; q < 8; q++) w[q] = fabsf(g_e1[s[q]] - e1d);
#pragma unroll
        for (int q = 0; q < 8; q++) {
            float4 v = h4conv(u[q]);
            sx += v.x; sy += v.y; sz += v.z; sw += v.w;
            mxx = fmaxf(mxx, v.x); mxy = fmaxf(mxy, v.y);
            mxz = fmaxf(mxz, v.z); mxw = fmaxf(mxw, v.w);
            dx = fmaf(w[q], v.x, dx); dy = fmaf(w[q], v.y, dy);
            dz = fmaf(w[q], v.z, dz); dw = fmaf(w[q], v.w, dw);
            wsum += w[q];
        }
    }
    for (; j < deg; j++) {
        int s0 = g_srcl[base + j];
        float w0 = fabsf(g_e1[s0] - e1d);
        float4 v0 = h4conv(h2[(size_t)s0 * 32 + lane]);
        sx += v0.x; sy += v0.y; sz += v0.z; sw += v0.w;
        mxx = fmaxf(mxx, v0.x); mxy = fmaxf(mxy, v0.y);
        mxz = fmaxf(mxz, v0.z); mxw = fmaxf(mxw, v0.w);
        dx = fmaf(w0, v0.x, dx); dy = fmaf(w0, v0.y, dy);
        dz = fmaf(w0, v0.z, dz); dw = fmaf(w0, v0.w, dw);
        wsum += w0;
    }

    float invd = 1.f / (float)(deg > 0 ? deg : 1);
    float invw = 1.f / (wsum + 1e-30f);
    if (deg == 0) { mxx = 0.f; mxy = 0.f; mxz = 0.f; mxw = 0.f; }

    uint2* o = reinterpret_cast<uint2*>(g_aggh) + (size_t)node * 96;
    o[lane]      = pack4(make_float4(sx * invd, sy * invd, sz * invd, sw * invd));
    o[32 + lane] = pack4(make_float4(mxx, mxy, mxz, mxw));
    o[64 + lane] = pack4(make_float4(dx * invw, dy * invw, dz * invw, dw * invw));
}

// ---------------- kernel 3: fused triple-B GEMM, BK=64, 2-stage --------------
#define BM 128
#define BN 64
#define BK 64
#define NKT (DAGG / BK)  // 6
#define A_STAGE 18432
#define B_OFF (2 * A_STAGE)
#define B_STAGE 27648
#define COEF_OFF (B_OFF + 2 * B_STAGE)
#define SMEM_BYTES (COEF_OFF + 3 * 128 * 4) // 93696

__global__ __launch_bounds__(256, 2) void k_gemm(
    const float* __restrict__ h, const float* __restrict__ snorm,
    const float* __restrict__ bias, const float* __restrict__ gamma,
    const float* __restrict__ beta, const float* __restrict__ mean,
    const float* __restrict__ var, float* __restrict__ out) {
    extern __shared__ char smc[];
    uint32_t sb = (uint32_t)__cvta_generic_to_shared(smc);
    float* samp = (float*)(smc + COEF_OFF);
    float* satt = samp + BM;
    float* ssn = satt + BM;

    int tid = threadIdx.x;
    int wid = tid >> 5;
    int lane = tid & 31;
    int t = lane & 3;
    int gid = lane >> 2;
    int wr = wid & 3;
    int wc = wid >> 2;
    int rowBlock = (blockIdx.x >> 1) * BM;
    int colBlock = (blockIdx.x & 1) * BN;

    for (int i = tid; i < BM; i += 256) {
        int r = rowBlock + i;
        float amp = 0.f, att = 0.f, sn = 0.f;
        if (r < NN) {
            int deg = g_cnt[r];
            float logD = logf((float)deg + 1.0f);
            amp = logD * (1.0f / AVG_D_LOG_F);
            att = fminf(AVG_D_LOG_F / fmaxf(logD, 1e-6f), 60000.f);
            sn = snorm[r];
        }
        samp[i] = amp;
        satt[i] = att;
        ssn[i] = sn;
    }

    const __half* a_src[4];
    uint32_t a_dst[4];
#pragma unroll
    for (int i = 0; i < 4; i++) {
        int c = tid + 256 * i;
        int row = c >> 3, kc = c & 7;
        int gr = rowBlock + row; if (gr > NN - 1) gr = NN - 1;
        a_src[i] = g_aggh + (size_t)gr * DAGG + kc * 8;
        a_dst[i] = sb + row * 144 + kc * 16;
    }

    const __half* b_src[6];
    uint32_t b_dst[6];
#pragma unroll
    for (int i = 0; i < 6; i++) {
        int c = tid + 256 * i;
        int g = c >> 9;
        int rem = c & 511;
        int krow = rem >> 3;
        int nc = rem & 7;
        b_src[i] = g_Wh + ((size_t)g * DAGG + krow) * D + colBlock + nc * 8;
        b_dst[i] = sb + B_OFF + g * 9216 + krow * 144 + nc * 16;
    }

    float c[2][4][4];
#pragma unroll
    for (int mt = 0; mt < 2; mt++)
#pragma unroll
        for (int nt = 0; nt < 4; nt++)
#pragma unroll
            for (int k = 0; k < 4; k++) c[mt][nt][k] = 0.f;

#pragma unroll
    for (int i = 0; i < 4; i++) cp16(a_dst[i], a_src[i]);
#pragma unroll
    for (int i = 0; i < 6; i++) cp16(b_dst[i], b_src[i]);
    asm volatile("cp.async.commit_group;\n");

    __syncthreads();

    uint32_t amp2[2][2], att2[2][2];
#pragma unroll
    for (int mt = 0; mt < 2; mt++) {
        int r0 = wr * 32 + mt * 16 + gid;
        __half2 a0 = __float2half2_rn(samp[r0]);
        __half2 a1 = __float2half2_rn(samp[r0 + 8]);
        __half2 t0 = __float2half2_rn(satt[r0]);
        __half2 t1 = __float2half2_rn(satt[r0 + 8]);
        amp2[mt][0] = *reinterpret_cast<uint32_t*>(&a0);
        amp2[mt][1] = *reinterpret_cast<uint32_t*>(&a1);
        att2[mt][0] = *reinterpret_cast<uint32_t*>(&t0);
        att2[mt][1] = *reinterpret_cast<uint32_t*>(&t1);
    }

    uint32_t a_lm = sb + (wr * 32 + (lane & 15)) * 144 + ((lane >> 4) << 4);
    uint32_t b_lm = sb + B_OFF + (lane & 15) * 144 + wc * 64 + ((lane >> 4) << 4);

    for (int kt = 0; kt < NKT; kt++) {
        int buf = kt & 1;
        if (kt + 1 < NKT) {
            size_t koff = (size_t)(kt + 1) * BK;
            uint32_t ao = (buf ^ 1) * A_STAGE;
#pragma unroll
            for (int i = 0; i < 4; i++) cp16(a_dst[i] + ao, a_src[i] + koff);
            uint32_t bo = (buf ^ 1) * B_STAGE;
#pragma unroll
            for (int i = 0; i < 6; i++) cp16(b_dst[i] + bo, b_src[i] + koff * D);
            asm volatile("cp.async.commit_group;\n");
            asm volatile("cp.async.wait_group 1;\n");
        } else {
            asm volatile("cp.async.wait_group 0;\n");
        }
        __syncthreads();

        uint32_t a_base = a_lm + buf * A_STAGE;
        uint32_t b_base = b_lm + buf * B_STAGE;
#pragma unroll
        for (int ks = 0; ks < 4; ks++) {
            uint32_t a[2][4];
            ldm_x4(a[0], a_base + ks * 32);
            ldm_x4(a[1], a_base + 16 * 144 + ks * 32);
#pragma unroll
            for (int g = 0; g < 3; g++) {
                uint32_t bfr[2][4];
#pragma unroll
                for (int p = 0; p < 2; p++)
                    ldm_x4t(bfr[p], b_base + g * 9216 + ks * 2304 + p * 32);
                uint32_t au[2][4];
#pragma unroll
                for (int mt = 0; mt < 2; mt++) {
                    if (g == 0) {
                        au[mt][0] = a[mt][0]; au[mt][1] = a[mt][1];
                        au[mt][2] = a[mt][2]; au[mt][3] = a[mt][3];
                    } else if (g == 1) {
                        au[mt][0] = hscale(a[mt][0], amp2[mt][0]);
                        au[mt][1] = hscale(a[mt][1], amp2[mt][1]);
                        au[mt][2] = hscale(a[mt][2], amp2[mt][0]);
                        au[mt][3] = hscale(a[mt][3], amp2[mt][1]);
                    } else {
                        au[mt][0] = hscale(a[mt][0], att2[mt][0]);
                        au[mt][1] = hscale(a[mt][1], att2[mt][1]);
                        au[mt][2] = hscale(a[mt][2], att2[mt][0]);
                        au[mt][3] = hscale(a[mt][3], att2[mt][1]);
                    }
                }
#pragma unroll
                for (int p = 0; p < 2; p++) {
#pragma unroll
                    for (int mt = 0; mt < 2; mt++) {
                        mma_f16(c[mt][p * 2], au[mt], bfr[p][0], bfr[p][1]);
                        mma_f16(c[mt][p * 2 + 1], au[mt], bfr[p][2], bfr[p][3]);
                    }
                }
            }
        }
        __syncthreads();
    }

    // fused epilogue
#pragma unroll
    for (int nt = 0; nt < 4; nt++) {
        int col = colBlock + wc * 32 + nt * 8 + 2 * t;
        float2 bi = *(const float2*)(bias + col);
        float2 mn = *(const float2*)(mean + col);
        float2 vr = *(const float2*)(var + col);
        float2 gm = *(const float2*)(gamma + col);
        float2 bt = *(const float2*)(beta + col);
        float sc0 = rsqrtf(vr.x + 1e-5f) * gm.x;
        float sc1 = rsqrtf(vr.y + 1e-5f) * gm.y;
        float sh0 = bt.x - mn.x * sc0;
        float sh1 = bt.y - mn.y * sc1;
#pragma unroll
        for (int mt = 0; mt < 2; mt++) {
#pragma unroll
            for (int p = 0; p < 2; p++) {
                int rloc = wr * 32 + mt * 16 + gid + p * 8;
                int r = rowBlock + rloc;
                if (r < NN) {
                    float sn = ssn[rloc];
                    float v0 = (c[mt][nt][p * 2 + 0] + bi.x) * sn;
                    float v1 = (c[mt][nt][p * 2 + 1] + bi.y) * sn;
                    v0 = fmaxf(fmaf(v0, sc0, sh0), 0.f);
                    v1 = fmaxf(fmaf(v1, sc1, sh1), 0.f);
                    float2 hres = *(const float2*)(h + (size_t)r * D + col);
                    *(float2*)(out + (size_t)r * D + col) =
                        make_float2(hres.x + v0, hres.y + v1);
                }
            }
        }
    }
}

// ---------------- launch ----------------------------------------------------
extern "C" void kernel_launch(void* const* d_in, const int* in_sizes, int n_in,
                              void* d_out, int out_size) {
    const float* h = (const float*)d_in[0];
    const float* eig = (const float*)d_in[1];
    const float* snorm = (const float*)d_in[2];
    const float* W = (const float*)d_in[3];
    const float* bias = (const float*)d_in[4];
    const float* gamma = (const float*)d_in[5];
    const float* beta = (const float*)d_in[6];
    const float* mean = (const float*)d_in[7];
    const float* var = (const float*)d_in[8];
    const int* esrc = (const int*)d_in[9];
    const int* edst = (const int*)d_in[10];
    float* out = (float*)d_out;

    // Host-side, non-stream, idempotent: capture-safe (no guard).
    cudaFuncSetAttribute(k_gemm, cudaFuncAttributeMaxDynamicSharedMemorySize,
                         SMEM_BYTES);

    void* cntPtr = nullptr;
    cudaGetSymbolAddress(&cntPtr, g_cnt);
    cudaMemsetAsync(cntPtr, 0, NN * sizeof(int));

    k_prepfill<<<PREPGRID, 256>>>((const int4*)esrc, (const int4*)edst, h, eig, W);
    k_reduce<<<(NN + 7) / 8, 256>>>();
    k_gemm<<<((NN + BM - 1) / BM) * 2, 256, SMEM_BYTES>>>(h, snorm, bias, gamma,
                                                          beta, mean, var, out);
}

// round 17
// speedup vs baseline: 1.1244x; 1.0111x over previous
#include <cuda_runtime.h>
#include <cuda_fp16.h>
#include <math.h>
#include <stdint.h>

#define NN 50000
#define EE 1600000
#define D 128
#define DAGG 384
#define DCAT 1152
#define CAP 128
#define AVG_D_LOG_F 3.4965075614664802f

// ---------------- static scratch --------------------------------------------
__device__ int g_cnt[NN];
__device__ __align__(16) int2 g_ent[(size_t)NN * CAP];      // {src, e1[src]}
__device__ float g_e1[NN];
__device__ __align__(16) __half g_hh[(size_t)NN * D];       // h in fp16
__device__ __align__(16) __half g_aggh[(size_t)NN * DAGG];  // agg fp16 [N,384]
__device__ __align__(16) __half g_Wh[(size_t)DCAT * D];     // W fp16 [1152,128]

// ---------------- helpers ---------------------------------------------------
__device__ __forceinline__ float4 h4conv(uint2 u) {
    __half2 a = *reinterpret_cast<__half2*>(&u.x);
    __half2 b = *reinterpret_cast<__half2*>(&u.y);
    float2 fa = __half22float2(a);
    float2 fb = __half22float2(b);
    return make_float4(fa.x, fa.y, fb.x, fb.y);
}

__device__ __forceinline__ uint2 pack4(float4 v) {
    uint2 r;
    __half2 lo = __floats2half2_rn(v.x, v.y);
    __half2 hi = __floats2half2_rn(v.z, v.w);
    r.x = *reinterpret_cast<uint32_t*>(&lo);
    r.y = *reinterpret_cast<uint32_t*>(&hi);
    return r;
}

__device__ __forceinline__ void mma_f16(float* c, const uint32_t* a,
                                        uint32_t b0, uint32_t b1) {
    asm volatile(
        "mma.sync.aligned.m16n8k16.row.col.f32.f16.f16.f32 "
        "{%0,%1,%2,%3}, {%4,%5,%6,%7}, {%8,%9}, {%0,%1,%2,%3};\n"
        : "+f"(c[0]), "+f"(c[1]), "+f"(c[2]), "+f"(c[3])
        : "r"(a[0]), "r"(a[1]), "r"(a[2]), "r"(a[3]), "r"(b0), "r"(b1));
}

__device__ __forceinline__ void ldm_x4(uint32_t* r, uint32_t addr) {
    asm volatile("ldmatrix.sync.aligned.m8n8.x4.shared.b16 {%0,%1,%2,%3}, [%4];"
                 : "=r"(r[0]), "=r"(r[1]), "=r"(r[2]), "=r"(r[3]) : "r"(addr));
}

__device__ __forceinline__ void ldm_x4t(uint32_t* r, uint32_t addr) {
    asm volatile("ldmatrix.sync.aligned.m8n8.x4.trans.shared.b16 {%0,%1,%2,%3}, [%4];"
                 : "=r"(r[0]), "=r"(r[1]), "=r"(r[2]), "=r"(r[3]) : "r"(addr));
}

__device__ __forceinline__ void cp16(uint32_t smem_addr, const void* gptr) {
    asm volatile("cp.async.cg.shared.global [%0], [%1], 16;\n"
                 :: "r"(smem_addr), "l"(gptr));
}

__device__ __forceinline__ uint32_t hscale(uint32_t a, uint32_t coef2) {
    __half2 r = __hmul2(*reinterpret_cast<__half2*>(&a),
                        *reinterpret_cast<__half2*>(&coef2));
    return *reinterpret_cast<uint32_t*>(&r);
}

// ---------------- kernel 1: fused prep + bucket fill (entries carry e1) -----
#define FILLB 782
#define HCONVB 1563
#define WCONVB 576
#define E1B 196
#define PREPGRID (FILLB + HCONVB + WCONVB + E1B)

__global__ void k_prepfill(const int4* __restrict__ src4, const int4* __restrict__ dst4,
                           const float* __restrict__ h, const float* __restrict__ eig,
                           const float* __restrict__ W) {
    int b = blockIdx.x;
    int t = threadIdx.x;
    if (b < FILLB) {
        int i = b * 256 + t;
        if (i >= 200000) return;
        int4 d0 = dst4[i];
        int4 s0 = src4[i];
        int4 d1 = dst4[i + 200000];
        int4 s1 = src4[i + 200000];
        // gather e1 of sources (scattered; overlaps with atomic latency)
        float e0x = eig[(size_t)s0.x * 4];
        float e0y = eig[(size_t)s0.y * 4];
        float e0z = eig[(size_t)s0.z * 4];
        float e0w = eig[(size_t)s0.w * 4];
        float e1x = eig[(size_t)s1.x * 4];
        float e1y = eig[(size_t)s1.y * 4];
        float e1z = eig[(size_t)s1.z * 4];
        float e1w = eig[(size_t)s1.w * 4];
        int p0 = atomicAdd(&g_cnt[d0.x], 1);
        int p1 = atomicAdd(&g_cnt[d0.y], 1);
        int p2 = atomicAdd(&g_cnt[d0.z], 1);
        int p3 = atomicAdd(&g_cnt[d0.w], 1);
        int p4 = atomicAdd(&g_cnt[d1.x], 1);
        int p5 = atomicAdd(&g_cnt[d1.y], 1);
        int p6 = atomicAdd(&g_cnt[d1.z], 1);
        int p7 = atomicAdd(&g_cnt[d1.w], 1);
        g_ent[(size_t)d0.x * CAP + p0] = make_int2(s0.x, __float_as_int(e0x));
        g_ent[(size_t)d0.y * CAP + p1] = make_int2(s0.y, __float_as_int(e0y));
        g_ent[(size_t)d0.z * CAP + p2] = make_int2(s0.z, __float_as_int(e0z));
        g_ent[(size_t)d0.w * CAP + p3] = make_int2(s0.w, __float_as_int(e0w));
        g_ent[(size_t)d1.x * CAP + p4] = make_int2(s1.x, __float_as_int(e1x));
        g_ent[(size_t)d1.y * CAP + p5] = make_int2(s1.y, __float_as_int(e1y));
        g_ent[(size_t)d1.z * CAP + p6] = make_int2(s1.z, __float_as_int(e1z));
        g_ent[(size_t)d1.w * CAP + p7] = make_int2(s1.w, __float_as_int(e1w));
    } else if (b < FILLB + HCONVB) {
        int i = (b - FILLB) * 256 + t;
        if (i >= 400000) return;
        const float4* h4 = (const float4*)h;
        uint2* o = (uint2*)g_hh;
#pragma unroll
        for (int r = 0; r < 4; r++) {
            int idx = i + r * 400000;
            float4 v = h4[idx];
            o[idx] = pack4(v);
        }
    } else if (b < FILLB + HCONVB + WCONVB) {
        int idx = (b - FILLB - HCONVB) * 256 + t;
        if (idx < DCAT * D)
            g_Wh[idx] = __float2half(W[idx]);
    } else {
        int idx = (b - FILLB - HCONVB - WCONVB) * 256 + t;
        if (idx < NN) g_e1[idx] = eig[(size_t)idx * 4];
    }
}

// ---------------- kernel 2: warp-per-node reduce (lane-loaded entries) ------
__global__ __launch_bounds__(256) void k_reduce() {
    int wid = threadIdx.x >> 5;
    int lane = threadIdx.x & 31;
    int node = blockIdx.x * 8 + wid;
    if (node >= NN) return;
    int deg = g_cnt[node];
    size_t base = (size_t)node * CAP;
    float e1d = g_e1[node];
    const uint2* h2 = reinterpret_cast<const uint2*>(g_hh);

    float sx = 0.f, sy = 0.f, sz = 0.f, sw = 0.f;
    float mxx = -3.402823466e38f, mxy = mxx, mxz = mxx, mxw = mxx;
    float dx = 0.f, dy = 0.f, dz = 0.f, dw = 0.f;
    float wsum = 0.f;

    int j = 0;
    for (; j + 8 <= deg; j += 8) {
        // 8 lanes cooperatively load the batch's 8 entries (64B, 2 sectors)
        int2 ent = make_int2(0, 0);
        if (lane < 8) ent = g_ent[base + j + lane];
        uint2 u[8];
        float w[8];
#pragma unroll
        for (int q = 0; q < 8; q++) {
            int s_q = __shfl_sync(0xffffffffu, ent.x, q);
            u[q] = h2[(size_t)s_q * 32 + lane];
        }
#pragma unroll
        for (int q = 0; q < 8; q++) {
            float e = __int_as_float(__shfl_sync(0xffffffffu, ent.y, q));
            w[q] = fabsf(e - e1d);
        }
#pragma unroll
        for (int q = 0; q < 8; q++) {
            float4 v = h4conv(u[q]);
            sx += v.x; sy += v.y; sz += v.z; sw += v.w;
            mxx = fmaxf(mxx, v.x); mxy = fmaxf(mxy, v.y);
            mxz = fmaxf(mxz, v.z); mxw = fmaxf(mxw, v.w);
            dx = fmaf(w[q], v.x, dx); dy = fmaf(w[q], v.y, dy);
            dz = fmaf(w[q], v.z, dz); dw = fmaf(w[q], v.w, dw);
            wsum += w[q];
        }
    }
    for (; j < deg; j++) {
        int2 e0 = g_ent[base + j];
        float w0 = fabsf(__int_as_float(e0.y) - e1d);
        float4 v0 = h4conv(h2[(size_t)e0.x * 32 + lane]);
        sx += v0.x; sy += v0.y; sz += v0.z; sw += v0.w;
        mxx = fmaxf(mxx, v0.x); mxy = fmaxf(mxy, v0.y);
        mxz = fmaxf(mxz, v0.z); mxw = fmaxf(mxw, v0.w);
        dx = fmaf(w0, v0.x, dx); dy = fmaf(w0, v0.y, dy);
        dz = fmaf(w0, v0.z, dz); dw = fmaf(w0, v0.w, dw);
        wsum += w0;
    }

    float invd = 1.f / (float)(deg > 0 ? deg : 1);
    float invw = 1.f / (wsum + 1e-30f);
    if (deg == 0) { mxx = 0.f; mxy = 0.f; mxz = 0.f; mxw = 0.f; }

    uint2* o = reinterpret_cast<uint2*>(g_aggh) + (size_t)node * 96;
    o[lane]      = pack4(make_float4(sx * invd, sy * invd, sz * invd, sw * invd));
    o[32 + lane] = pack4(make_float4(mxx, mxy, mxz, mxw));
    o[64 + lane] = pack4(make_float4(dx * invw, dy * invw, dz * invw, dw * invw));
}

// ---------------- kernel 3: fused triple-B GEMM, BK=64, 2-stage --------------
#define BM 128
#define BN 64
#define BK 64
#define NKT (DAGG / BK)  // 6
#define A_STAGE 18432
#define B_OFF (2 * A_STAGE)
#define B_STAGE 27648
#define COEF_OFF (B_OFF + 2 * B_STAGE)
#define SMEM_BYTES (COEF_OFF + 3 * 128 * 4) // 93696

__global__ __launch_bounds__(256, 2) void k_gemm(
    const float* __restrict__ h, const float* __restrict__ snorm,
    const float* __restrict__ bias, const float* __restrict__ gamma,
    const float* __restrict__ beta, const float* __restrict__ mean,
    const float* __restrict__ var, float* __restrict__ out) {
    extern __shared__ char smc[];
    uint32_t sb = (uint32_t)__cvta_generic_to_shared(smc);
    float* samp = (float*)(smc + COEF_OFF);
    float* satt = samp + BM;
    float* ssn = satt + BM;

    int tid = threadIdx.x;
    int wid = tid >> 5;
    int lane = tid & 31;
    int t = lane & 3;
    int gid = lane >> 2;
    int wr = wid & 3;
    int wc = wid >> 2;
    int rowBlock = (blockIdx.x >> 1) * BM;
    int colBlock = (blockIdx.x & 1) * BN;

    for (int i = tid; i < BM; i += 256) {
        int r = rowBlock + i;
        float amp = 0.f, att = 0.f, sn = 0.f;
        if (r < NN) {
            int deg = g_cnt[r];
            float logD = logf((float)deg + 1.0f);
            amp = logD * (1.0f / AVG_D_LOG_F);
            att = fminf(AVG_D_LOG_F / fmaxf(logD, 1e-6f), 60000.f);
            sn = snorm[r];
        }
        samp[i] = amp;
        satt[i] = att;
        ssn[i] = sn;
    }

    const __half* a_src[4];
    uint32_t a_dst[4];
#pragma unroll
    for (int i = 0; i < 4; i++) {
        int c = tid + 256 * i;
        int row = c >> 3, kc = c & 7;
        int gr = rowBlock + row; if (gr > NN - 1) gr = NN - 1;
        a_src[i] = g_aggh + (size_t)gr * DAGG + kc * 8;
        a_dst[i] = sb + row * 144 + kc * 16;
    }

    const __half* b_src[6];
    uint32_t b_dst[6];
#pragma unroll
    for (int i = 0; i < 6; i++) {
        int c = tid + 256 * i;
        int g = c >> 9;
        int rem = c & 511;
        int krow = rem >> 3;
        int nc = rem & 7;
        b_src[i] = g_Wh + ((size_t)g * DAGG + krow) * D + colBlock + nc * 8;
        b_dst[i] = sb + B_OFF + g * 9216 + krow * 144 + nc * 16;
    }

    float c[2][4][4];
#pragma unroll
    for (int mt = 0; mt < 2; mt++)
#pragma unroll
        for (int nt = 0; nt < 4; nt++)
#pragma unroll
            for (int k = 0; k < 4; k++) c[mt][nt][k] = 0.f;

#pragma unroll
    for (int i = 0; i < 4; i++) cp16(a_dst[i], a_src[i]);
#pragma unroll
    for (int i = 0; i < 6; i++) cp16(b_dst[i], b_src[i]);
    asm volatile("cp.async.commit_group;\n");

    __syncthreads();

    uint32_t amp2[2][2], att2[2][2];
#pragma unroll
    for (int mt = 0; mt < 2; mt++) {
        int r0 = wr * 32 + mt * 16 + gid;
        __half2 a0 = __float2half2_rn(samp[r0]);
        __half2 a1 = __float2half2_rn(samp[r0 + 8]);
        __half2 t0 = __float2half2_rn(satt[r0]);
        __half2 t1 = __float2half2_rn(satt[r0 + 8]);
        amp2[mt][0] = *reinterpret_cast<uint32_t*>(&a0);
        amp2[mt][1] = *reinterpret_cast<uint32_t*>(&a1);
        att2[mt][0] = *reinterpret_cast<uint32_t*>(&t0);
        att2[mt][1] = *reinterpret_cast<uint32_t*>(&t1);
    }

    uint32_t a_lm = sb + (wr * 32 + (lane & 15)) * 144 + ((lane >> 4) << 4);
    uint32_t b_lm = sb + B_OFF + (lane & 15) * 144 + wc * 64 + ((lane >> 4) << 4);

    for (int kt = 0; kt < NKT; kt++) {
        int buf = kt & 1;
        if (kt + 1 < NKT) {
            size_t koff = (size_t)(kt + 1) * BK;
            uint32_t ao = (buf ^ 1) * A_STAGE;
#pragma unroll
            for (int i = 0; i < 4; i++) cp16(a_dst[i] + ao, a_src[i] + koff);
            uint32_t bo = (buf ^ 1) * B_STAGE;
#pragma unroll
            for (int i = 0; i < 6; i++) cp16(b_dst[i] + bo, b_src[i] + koff * D);
            asm volatile("cp.async.commit_group;\n");
            asm volatile("cp.async.wait_group 1;\n");
        } else {
            asm volatile("cp.async.wait_group 0;\n");
        }
        __syncthreads();

        uint32_t a_base = a_lm + buf * A_STAGE;
        uint32_t b_base = b_lm + buf * B_STAGE;
#pragma unroll
        for (int ks = 0; ks < 4; ks++) {
            uint32_t a[2][4];
            ldm_x4(a[0], a_base + ks * 32);
            ldm_x4(a[1], a_base + 16 * 144 + ks * 32);
#pragma unroll
            for (int g = 0; g < 3; g++) {
                uint32_t bfr[2][4];
#pragma unroll
                for (int p = 0; p < 2; p++)
                    ldm_x4t(bfr[p], b_base + g * 9216 + ks * 2304 + p * 32);
                uint32_t au[2][4];
#pragma unroll
                for (int mt = 0; mt < 2; mt++) {
                    if (g == 0) {
                        au[mt][0] = a[mt][0]; au[mt][1] = a[mt][1];
                        au[mt][2] = a[mt][2]; au[mt][3] = a[mt][3];
                    } else if (g == 1) {
                        au[mt][0] = hscale(a[mt][0], amp2[mt][0]);
                        au[mt][1] = hscale(a[mt][1], amp2[mt][1]);
                        au[mt][2] = hscale(a[mt][2], amp2[mt][0]);
                        au[mt][3] = hscale(a[mt][3], amp2[mt][1]);
                    } else {
                        au[mt][0] = hscale(a[mt][0], att2[mt][0]);
                        au[mt][1] = hscale(a[mt][1], att2[mt][1]);
                        au[mt][2] = hscale(a[mt][2], att2[mt][0]);
                        au[mt][3] = hscale(a[mt][3], att2[mt][1]);
                    }
                }
#pragma unroll
                for (int p = 0; p < 2; p++) {
#pragma unroll
                    for (int mt = 0; mt < 2; mt++) {
                        mma_f16(c[mt][p * 2], au[mt], bfr[p][0], bfr[p][1]);
                        mma_f16(c[mt][p * 2 + 1], au[mt], bfr[p][2], bfr[p][3]);
                    }
                }
            }
        }
        __syncthreads();
    }

    // fused epilogue
#pragma unroll
    for (int nt = 0; nt < 4; nt++) {
        int col = colBlock + wc * 32 + nt * 8 + 2 * t;
        float2 bi = *(const float2*)(bias + col);
        float2 mn = *(const float2*)(mean + col);
        float2 vr = *(const float2*)(var + col);
        float2 gm = *(const float2*)(gamma + col);
        float2 bt = *(const float2*)(beta + col);
        float sc0 = rsqrtf(vr.x + 1e-5f) * gm.x;
        float sc1 = rsqrtf(vr.y + 1e-5f) * gm.y;
        float sh0 = bt.x - mn.x * sc0;
        float sh1 = bt.y - mn.y * sc1;
#pragma unroll
        for (int mt = 0; mt < 2; mt++) {
#pragma unroll
            for (int p = 0; p < 2; p++) {
                int rloc = wr * 32 + mt * 16 + gid + p * 8;
                int r = rowBlock + rloc;
                if (r < NN) {
                    float sn = ssn[rloc];
                    float v0 = (c[mt][nt][p * 2 + 0] + bi.x) * sn;
                    float v1 = (c[mt][nt][p * 2 + 1] + bi.y) * sn;
                    v0 = fmaxf(fmaf(v0, sc0, sh0), 0.f);
                    v1 = fmaxf(fmaf(v1, sc1, sh1), 0.f);
                    float2 hres = *(const float2*)(h + (size_t)r * D + col);
                    *(float2*)(out + (size_t)r * D + col) =
                        make_float2(hres.x + v0, hres.y + v1);
                }
            }
        }
    }
}

// ---------------- launch ----------------------------------------------------
extern "C" void kernel_launch(void* const* d_in, const int* in_sizes, int n_in,
                              void* d_out, int out_size) {
    const float* h = (const float*)d_in[0];
    const float* eig = (const float*)d_in[1];
    const float* snorm = (const float*)d_in[2];
    const float* W = (const float*)d_in[3];
    const float* bias = (const float*)d_in[4];
    const float* gamma = (const float*)d_in[5];
    const float* beta = (const float*)d_in[6];
    const float* mean = (const float*)d_in[7];
    const float* var = (const float*)d_in[8];
    const int* esrc = (const int*)d_in[9];
    const int* edst = (const int*)d_in[10];
    float* out = (float*)d_out;

    // Host-side, non-stream, idempotent: capture-safe (no guard).
    cudaFuncSetAttribute(k_gemm, cudaFuncAttributeMaxDynamicSharedMemorySize,
                         SMEM_BYTES);

    void* cntPtr = nullptr;
    cudaGetSymbolAddress(&cntPtr, g_cnt);
    cudaMemsetAsync(cntPtr, 0, NN * sizeof(int));

    k_prepfill<<<PREPGRID, 256>>>((const int4*)esrc, (const int4*)edst, h, eig, W);
    k_reduce<<<(NN + 7) / 8, 256>>>();
    k_gemm<<<((NN + BM - 1) / BM) * 2, 256, SMEM_BYTES>>>(h, snorm, bias, gamma,
                                                          beta, mean, var, out);
}